// round 7
// baseline (speedup 1.0000x reference)
#include <cuda_runtime.h>
#include <cstdint>

// ROI-align pooling, R6: TMA-path bulk loads + SMEM double buffer.
// img (1,128,128,1024) NHWC fp32, rois (1,256,4), out (1,256,7,7,1024) fp32.
//
// setup_kernel: per bin, compute unique corner pixel offsets (1..4 of them),
//   a logical-corner -> smem-slot map, and (tx,ty).
// roi_pool_kernel: 1184 persistent blocks x 256 threads, ~11 bins each.
//   Producer (tid 0) issues cp.async.bulk 4KB copies for the NEXT bin into
//   the alternate smem stage while everyone computes the CURRENT bin from
//   smem (LDS.128) and stores via STG.128. Global loads bypass the per-lane
//   L1tex wavefront path entirely.

#define POOL  7
#define NROIS 256
#define HH    128
#define WW    128
#define CC    1024
#define NBINS (NROIS * POOL * POOL)   // 12544
#define GRID  1184

__device__ int4   g_offs[NBINS];   // unique corner offsets (float4 units), slots 0..ucnt-1
__device__ int4   g_map[NBINS];    // logical corner (00,01,10,11) -> slot index
__device__ float2 g_ts[NBINS];     // (tx, ty)

__global__ void setup_kernel(const float* __restrict__ rois)
{
    const int bin = blockIdx.x * blockDim.x + threadIdx.x;
    if (bin >= NBINS) return;

    const int roi = bin / (POOL * POOL);
    const int b49 = bin - roi * (POOL * POOL);
    const int iy  = b49 / POOL;
    const int ix  = b49 - iy * POOL;

    const float4 r = reinterpret_cast<const float4*>(rois)[roi];
    const int x0 = (int)(r.x * 0.0625f);
    const int y0 = (int)(r.y * 0.0625f);
    const int w  = (int)(r.z * 0.0625f);
    const int h  = (int)(r.w * 0.0625f);

    // identical fp32 math to reference
    const float sy = (float)iy * ((float)h / (float)POOL);
    const float sx = (float)ix * ((float)w / (float)POOL);
    const float fy = floorf(sy);
    const float fx = floorf(sx);
    const float ty = sy - fy;
    const float tx = sx - fx;

    const int y_lo = (int)fy;
    const int x_lo = (int)fx;
    const int y_hi = min(y_lo + 1, max(h - 1, 0));
    const int x_hi = min(x_lo + 1, max(w - 1, 0));

    const int gy0 = min(max(y0 + y_lo, 0), HH - 1);
    const int gy1 = min(max(y0 + y_hi, 0), HH - 1);
    const int gx0 = min(max(x0 + x_lo, 0), WW - 1);
    const int gx1 = min(max(x0 + x_hi, 0), WW - 1);

    // hi corner collapses onto lo when weight is exactly 0 or clamp makes it
    // bitwise identical (bit-exact result either way).
    const bool needx = (tx != 0.0f) && (gx1 != gx0);
    const bool needy = (ty != 0.0f) && (gy1 != gy0);
    const int ex = needx ? gx1 : gx0;
    const int ey = needy ? gy1 : gy0;

    const int c4 = CC / 4;
    const int o00 = (gy0 * WW + gx0) * c4;
    const int o01 = (gy0 * WW + ex ) * c4;
    const int o10 = (ey  * WW + gx0) * c4;
    const int o11 = (ey  * WW + ex ) * c4;

    int4 offs, map;
    if (!needx && !needy) { offs = make_int4(o00, o00, o00, o00); map = make_int4(0, 0, 0, 0); }
    else if (!needx)      { offs = make_int4(o00, o10, o10, o10); map = make_int4(0, 0, 1, 1); }
    else if (!needy)      { offs = make_int4(o00, o01, o01, o01); map = make_int4(0, 1, 0, 1); }
    else                  { offs = make_int4(o00, o01, o10, o11); map = make_int4(0, 1, 2, 3); }

    g_offs[bin] = offs;
    g_map[bin]  = map;           // ucnt = map.w + 1
    g_ts[bin]   = make_float2(tx, ty);
}

__device__ __forceinline__ uint32_t smem_u32(const void* p)
{
    return (uint32_t)__cvta_generic_to_shared(p);
}

__device__ __forceinline__ void bulk_g2s(uint32_t dst, const void* src,
                                         uint32_t bytes, uint32_t mbar)
{
    asm volatile(
        "cp.async.bulk.shared::cta.global.mbarrier::complete_tx::bytes "
        "[%0], [%1], %2, [%3];"
        :: "r"(dst), "l"(src), "r"(bytes), "r"(mbar) : "memory");
}

__device__ __forceinline__ void mbar_init(uint32_t mbar, uint32_t count)
{
    asm volatile("mbarrier.init.shared.b64 [%0], %1;" :: "r"(mbar), "r"(count) : "memory");
}

__device__ __forceinline__ void mbar_expect_tx(uint32_t mbar, uint32_t bytes)
{
    asm volatile("mbarrier.arrive.expect_tx.shared.b64 _, [%0], %1;"
                 :: "r"(mbar), "r"(bytes) : "memory");
}

__device__ __forceinline__ void mbar_wait(uint32_t mbar, uint32_t parity)
{
    asm volatile(
        "{\n\t"
        ".reg .pred P1;\n\t"
        "WAIT_LOOP_%=:\n\t"
        "mbarrier.try_wait.parity.acquire.cta.shared::cta.b64 P1, [%0], %1, 0x989680;\n\t"
        "@P1 bra.uni WAIT_DONE_%=;\n\t"
        "bra.uni WAIT_LOOP_%=;\n\t"
        "WAIT_DONE_%=:\n\t"
        "}"
        :: "r"(mbar), "r"(parity) : "memory");
}

__global__ __launch_bounds__(256, 6)
void roi_pool_kernel(const float* __restrict__ img,
                     float* __restrict__ out)
{
    __shared__ __align__(16) float4 buf[2][4][CC / 4];  // 2 stages x 4 corners x 4KB
    __shared__ __align__(8) unsigned long long mbar_s[2];

    const int t = threadIdx.x;
    float4* __restrict__ outv = reinterpret_cast<float4*>(out);

    const uint32_t mb0 = smem_u32(&mbar_s[0]);
    const uint32_t mb1 = smem_u32(&mbar_s[1]);

    if (t == 0) { mbar_init(mb0, 1); mbar_init(mb1, 1); }
    __syncthreads();

    // prologue: issue copies for first bin into stage 0
    if (t == 0) {
        const int bin0 = blockIdx.x;
        const int4 offs = g_offs[bin0];
        const int ucnt  = g_map[bin0].w + 1;
        mbar_expect_tx(mb0, (uint32_t)ucnt * 4096u);
        const int oarr[4] = { offs.x, offs.y, offs.z, offs.w };
        for (int u = 0; u < ucnt; u++)
            bulk_g2s(smem_u32(&buf[0][u][0]),
                     (const char*)img + (size_t)oarr[u] * 16, 4096u, mb0);
    }

    int phase0 = 0, phase1 = 0;
    int k = 0;
    while (true) {
        const int s    = k & 1;
        const int bin  = blockIdx.x + k * GRID;
        const int nbin = bin + GRID;

        // producer: issue NEXT bin's copies into the other stage.
        // Safe: that stage was last consumed at iteration k-1, which ended
        // with __syncthreads() that we're past.
        if (t == 0 && nbin < NBINS) {
            const uint32_t mbn = (s == 0) ? mb1 : mb0;
            const int4 offs = g_offs[nbin];
            const int ucnt  = g_map[nbin].w + 1;
            mbar_expect_tx(mbn, (uint32_t)ucnt * 4096u);
            const int oarr[4] = { offs.x, offs.y, offs.z, offs.w };
            for (int u = 0; u < ucnt; u++)
                bulk_g2s(smem_u32(&buf[s ^ 1][u][0]),
                         (const char*)img + (size_t)oarr[u] * 16, 4096u, mbn);
        }

        // wait current stage full
        if (s == 0) { mbar_wait(mb0, phase0); phase0 ^= 1; }
        else        { mbar_wait(mb1, phase1); phase1 ^= 1; }

        // compute current bin from smem
        const int4   map = g_map[bin];
        const float2 tw  = g_ts[bin];
        const float  tx = tw.x, ty = tw.y;

        const float4 a = buf[s][map.x][t];
        const float4 b = buf[s][map.y][t];
        const float4 c = buf[s][map.z][t];
        const float4 d = buf[s][map.w][t];

        float4 r;
        {
            float top, bot;
            top = a.x + tx * (b.x - a.x);
            bot = c.x + tx * (d.x - c.x);
            r.x = top + ty * (bot - top);
            top = a.y + tx * (b.y - a.y);
            bot = c.y + tx * (d.y - c.y);
            r.y = top + ty * (bot - top);
            top = a.z + tx * (b.z - a.z);
            bot = c.z + tx * (d.z - c.z);
            r.z = top + ty * (bot - top);
            top = a.w + tx * (b.w - a.w);
            bot = c.w + tx * (d.w - c.w);
            r.w = top + ty * (bot - top);
        }
        outv[(size_t)bin * (CC / 4) + t] = r;

        if (nbin >= NBINS) break;
        __syncthreads();   // all reads of stage s done -> reusable at k+2
        k++;
    }
}

extern "C" void kernel_launch(void* const* d_in, const int* in_sizes, int n_in,
                              void* d_out, int out_size)
{
    const float* img  = (const float*)d_in[0];
    const float* rois = (const float*)d_in[1];
    if (n_in >= 2 && in_sizes[0] < in_sizes[1]) {
        img  = (const float*)d_in[1];
        rois = (const float*)d_in[0];
    }
    float* out = (float*)d_out;

    setup_kernel<<<(NBINS + 255) / 256, 256>>>(rois);
    roi_pool_kernel<<<GRID, 256>>>(img, out);
}